// round 16
// baseline (speedup 1.0000x reference)
#include <cuda_runtime.h>
#include <cuda_bf16.h>
#include <math.h>
#include <stdint.h>

// ---------------- problem constants ----------------
#define BATCH 8
#define TSTEPS 16
#define CIN0 192
#define HC0 64
#define HC1 32
#define HC2 64
#define IMG_H 28
#define IMG_W 28
#define HW 784

// ---------------- device scratch (no allocs allowed) ----------------
__device__ float g_gx0[(size_t)BATCH * TSTEPS * 4 * HC0 * HW];

#define SZ0 (BATCH * HC0 * HW)
#define SZ1 (BATCH * HC1 * HW)
#define SZ2 (BATCH * HC2 * HW)
#define OFF_H0A 0
#define OFF_H0B (OFF_H0A + SZ0)
#define OFF_C0  (OFF_H0B + SZ0)
#define OFF_H1A (OFF_C0  + SZ0)
#define OFF_H1B (OFF_H1A + SZ1)
#define OFF_C1  (OFF_H1B + SZ1)
#define OFF_H2A (OFF_C1  + SZ1)
#define OFF_H2B (OFF_H2A + SZ2)
#define OFF_C2  (OFF_H2B + SZ2)
#define NSTATE  (OFF_C2  + SZ2)
__device__ float g_state[NSTATE];

// pre-transposed tf32 weight buffers, layout [y][chunk][tap][m(32)][ci(8)]
// oc(m) = (m>>3)*HC + y*8 + (m&7)          (R5 layout, bit-identical)
#define WPC 2304
#define WOFF_GX0 0
#define WSZ_GX0 (8 * 24 * WPC)
#define WOFF_L0 (WOFF_GX0 + WSZ_GX0)
#define WSZ_L0  (8 * 8 * WPC)
#define WOFF_L1 (WOFF_L0 + WSZ_L0)
#define WSZ_L1  (4 * 12 * WPC)
#define WOFF_L2 (WOFF_L1 + WSZ_L1)
#define WSZ_L2  (8 * 12 * WPC)
#define WTOTAL  (WOFF_L2 + WSZ_L2)
__device__ uint32_t g_wt[WTOTAL];

__global__ void init_zero_kernel(float* p, int n) {
    int i = blockIdx.x * blockDim.x + threadIdx.x;
    if (i < n) p[i] = 0.f;
}

// ---------------- tf32 / PDL helpers ----------------
__device__ __forceinline__ uint32_t f2tf32(float f) {
    uint32_t u;
    asm("cvt.rna.tf32.f32 %0, %1;" : "=r"(u) : "f"(f));
    return u;
}

__device__ __forceinline__ void pdl_launch_dependents() {
    asm volatile("griddepcontrol.launch_dependents;");
}
__device__ __forceinline__ void pdl_wait() {
    asm volatile("griddepcontrol.wait;" ::: "memory");
}

__device__ __forceinline__ void mma_tf32(float c[4],
                                         uint32_t a0, uint32_t a1, uint32_t a2, uint32_t a3,
                                         uint32_t b0, uint32_t b1) {
    asm volatile(
        "mma.sync.aligned.m16n8k8.row.col.f32.tf32.tf32.f32 "
        "{%0,%1,%2,%3}, {%4,%5,%6,%7}, {%8,%9}, {%0,%1,%2,%3};"
        : "+f"(c[0]), "+f"(c[1]), "+f"(c[2]), "+f"(c[3])
        : "r"(a0), "r"(a1), "r"(a2), "r"(a3), "r"(b0), "r"(b1));
}

__device__ __forceinline__ float sigmoidf_(float x) {
    return 1.0f / (1.0f + __expf(-x));
}

// ---------------- fused weight prep: all 4 sets in ONE launch ---------------
__device__ __forceinline__ void prep_one(
    const float* __restrict__ WA, int cinA,
    const float* __restrict__ WB, int cinB,
    int HC, int chunks, uint32_t* __restrict__ dst, int idx)
{
    int ci  = idx & 7;
    int m   = (idx >> 3) & 31;
    int tap = (idx >> 8) % 9;
    int chy = idx / WPC;
    int ch  = chy % chunks;
    int y   = chy / chunks;
    int oc  = (m >> 3) * HC + y * 8 + (m & 7);
    int cg  = ch * 8 + ci;
    float w;
    if (cg < cinA) w = WA[((size_t)oc * cinA + cg) * 9 + tap];
    else           w = WB[((size_t)oc * cinB + (cg - cinA)) * 9 + tap];
    dst[idx] = f2tf32(w);
}

__global__ void prep_all(
    const float* __restrict__ Wx0, const float* __restrict__ Wh0,
    const float* __restrict__ Wx1, const float* __restrict__ Wh1,
    const float* __restrict__ Wx2, const float* __restrict__ Wh2,
    uint32_t* __restrict__ wt)
{
    int i = blockIdx.x * blockDim.x + threadIdx.x;
    if (i < WSZ_GX0) { prep_one(Wx0, CIN0, nullptr, 0, HC0, 24, wt + WOFF_GX0, i); return; }
    i -= WSZ_GX0;
    if (i < WSZ_L0)  { prep_one(Wh0, HC0,  nullptr, 0, HC0,  8, wt + WOFF_L0,  i); return; }
    i -= WSZ_L0;
    if (i < WSZ_L1)  { prep_one(Wx1, HC0,  Wh1, HC1, HC1, 12, wt + WOFF_L1,  i); return; }
    i -= WSZ_L1;
    if (i < WSZ_L2)  { prep_one(Wx2, HC1,  Wh2, HC2, HC2, 12, wt + WOFF_L2,  i); }
}
#define PREP_TOTAL WTOTAL

// ---------------- conv 3x3 + fused LSTM (R5 engine + PDL prelude) -----------
#define SIN_STR 200

struct SmemU {
    union {
        struct {
            uint32_t in[2][8 * SIN_STR];
            uint32_t w[2][WPC];
        } mm;
        float gates[4 * 8 * 112];
    };
};

__global__ void __launch_bounds__(128, 4) conv3x3_cell(
    const float* __restrict__ inA, int cinA, size_t inAStride,
    const float* __restrict__ inB, int cinB,
    const uint32_t* __restrict__ wt,
    const float* __restrict__ bias,
    const float* __restrict__ pre, size_t preStride,
    int HC,
    float* __restrict__ out, size_t outStride,   // plain path (hout == nullptr)
    const float* __restrict__ Wp,
    float* __restrict__ hout, float* __restrict__ c,
    float* __restrict__ yout, int t)
{
    __shared__ SmemU sm;

    // PDL: we write nothing a successor reads before its own wait; let it begin.
    pdl_launch_dependents();

    const int n       = blockIdx.x;
    const int yb      = blockIdx.y;
    const int hcb     = yb * 8;
    const int rowbase = blockIdx.z * 4;

    const int tid    = threadIdx.x;
    const int lane   = tid & 31;
    const int wid    = tid >> 5;
    const int warp_m = wid & 1;
    const int warp_n = wid >> 1;
    const int g      = lane >> 2;
    const int ctg    = lane & 3;

    const int chunks = (cinA + cinB) >> 3;

    int off[7];
#pragma unroll
    for (int s = 0; s < 7; ++s) {
        int nl = warp_n * 56 + s * 8 + g;
        int r = nl / 28;
        off[s] = r * 30 + (nl - r * 28);
    }

    float acc[7][4];
#pragma unroll
    for (int s = 0; s < 7; ++s)
#pragma unroll
        for (int j = 0; j < 4; ++j) acc[s][j] = 0.f;

    float rin[12];
    uint4 rw4[5];

    // weights are immutable after prep: safe to prefetch BEFORE the PDL wait
    auto load_w = [&](int ch) {
        const uint4* wsrc = (const uint4*)(wt + ((size_t)yb * chunks + ch) * WPC);
#pragma unroll
        for (int k = 0; k < 5; ++k) {
            int i4 = tid + k * 128;
            if (i4 < 576) rw4[k] = wsrc[i4];
        }
    };

    auto load_in = [&](int ch) {
        const int cstart = ch * 8;
        const float* src = (cstart < cinA)
            ? inA + (size_t)n * inAStride + (size_t)cstart * HW
            : inB + ((size_t)n * cinB + (cstart - cinA)) * HW;
#pragma unroll
        for (int k = 0; k < 12; ++k) {
            int idx = tid + k * 128;
            float v = 0.f;
            if (idx < 1440) {
                int ci  = idx / 180;
                int rem = idx - ci * 180;
                int pr  = rem / 30;
                int gr  = rowbase + pr - 1;
                int gc  = (rem - pr * 30) - 1;
                if (gr >= 0 && gr < IMG_H && gc >= 0 && gc < IMG_W)
                    v = src[(size_t)ci * HW + gr * IMG_W + gc];
            }
            rin[k] = v;
        }
    };

    load_w(0);        // independent prelude (overlaps predecessor execution)
    pdl_wait();       // all predecessors complete -> mutable inputs safe
    load_in(0);

    for (int ch = 0; ch < chunks; ++ch) {
        const int st = ch & 1;
#pragma unroll
        for (int k = 0; k < 12; ++k) {
            int idx = tid + k * 128;
            if (idx < 1440) {
                int ci  = idx / 180;
                int rem = idx - ci * 180;
                sm.mm.in[st][ci * SIN_STR + rem] = f2tf32(rin[k]);
            }
        }
#pragma unroll
        for (int k = 0; k < 5; ++k) {
            int i4 = tid + k * 128;
            if (i4 < 576) ((uint4*)sm.mm.w[st])[i4] = rw4[k];
        }
        __syncthreads();

        if (ch + 1 < chunks) { load_w(ch + 1); load_in(ch + 1); }  // overlaps MMA

        const uint32_t* win = sm.mm.in[st];
        const uint32_t* ww  = sm.mm.w[st];
#pragma unroll
        for (int kr = 0; kr < 3; ++kr) {
#pragma unroll
            for (int kc = 0; kc < 3; ++kc) {
                const int tap = kr * 3 + kc;
                const uint32_t* wp = ww + tap * 256 + (warp_m * 16 + g) * 8 + ctg;
                uint32_t a0 = wp[0];
                uint32_t a1 = wp[64];
                uint32_t a2 = wp[4];
                uint32_t a3 = wp[68];
                const int bbase = ctg * SIN_STR + kr * 30 + kc;
#pragma unroll
                for (int s = 0; s < 7; ++s) {
                    uint32_t b0 = win[bbase + off[s]];
                    uint32_t b1 = win[bbase + off[s] + 4 * SIN_STR];
                    mma_tf32(acc[s], a0, a1, a2, a3, b0, b1);
                }
            }
        }
    }

    // ---- epilogue ----
    const int m0  = warp_m * 16 + g;
    const int oc0 = (m0 >> 3) * HC + hcb + (m0 & 7);
    const int m1  = m0 + 8;
    const int oc1 = (m1 >> 3) * HC + hcb + (m1 & 7);
    float bv0 = 0.f, bv1 = 0.f;
    if (bias) { bv0 = bias[oc0]; bv1 = bias[oc1]; }

    if (hout == nullptr) {
#pragma unroll
        for (int s = 0; s < 7; ++s) {
#pragma unroll
            for (int j = 0; j < 2; ++j) {
                int nl = warp_n * 56 + s * 8 + 2 * ctg + j;
                int r = nl / 28;
                int px = (rowbase + r) * IMG_W + (nl - r * 28);
                float v0 = acc[s][j]     + bv0;
                float v1 = acc[s][2 + j] + bv1;
                if (pre) {
                    v0 += pre[(size_t)n * preStride + (size_t)oc0 * HW + px];
                    v1 += pre[(size_t)n * preStride + (size_t)oc1 * HW + px];
                }
                out[(size_t)n * outStride + (size_t)oc0 * HW + px] = v0;
                out[(size_t)n * outStride + (size_t)oc1 * HW + px] = v1;
            }
        }
        return;
    }

    // fused LSTM: exchange gates through smem, then pointwise
    __syncthreads();
#pragma unroll
    for (int s = 0; s < 7; ++s) {
#pragma unroll
        for (int j = 0; j < 2; ++j) {
            int nl = warp_n * 56 + s * 8 + 2 * ctg + j;
            float v0 = acc[s][j]     + bv0;
            float v1 = acc[s][2 + j] + bv1;
            if (pre) {
                int r = nl / 28;
                int px = (rowbase + r) * IMG_W + (nl - r * 28);
                v0 += pre[(size_t)n * preStride + (size_t)oc0 * HW + px];
                v1 += pre[(size_t)n * preStride + (size_t)oc1 * HW + px];
            }
            sm.gates[((m0 >> 3) * 8 + (m0 & 7)) * 112 + nl] = v0;
            sm.gates[((m1 >> 3) * 8 + (m1 & 7)) * 112 + nl] = v1;
        }
    }
    __syncthreads();

#pragma unroll
    for (int k = 0; k < 7; ++k) {
        int e   = tid + k * 128;
        int hcl = e / 112;
        int nl  = e - hcl * 112;
        int r   = nl / 28;
        int px  = (rowbase + r) * IMG_W + (nl - r * 28);
        int hc  = hcb + hcl;

        float g0 = sm.gates[(0 * 8 + hcl) * 112 + nl];
        float g1 = sm.gates[(1 * 8 + hcl) * 112 + nl];
        float g2 = sm.gates[(2 * 8 + hcl) * 112 + nl];
        float g3 = sm.gates[(3 * 8 + hcl) * 112 + nl];

        size_t sidx = ((size_t)n * HC + hc) * HW + px;
        float cv = c[sidx];
        float pi = Wp[(size_t)(0 * HC + hc) * HW + px];
        float pf = Wp[(size_t)(1 * HC + hc) * HW + px];
        float po = Wp[(size_t)(2 * HC + hc) * HW + px];

        float gi = sigmoidf_(g0 + cv * pi);
        float gf = sigmoidf_(g1 + cv * pf);
        float cc = gf * cv + gi * tanhf(g2);
        float go = sigmoidf_(g3 + cc * po);
        float hv = go * tanhf(cc);

        c[sidx] = cc;
        hout[sidx] = hv;
        if (yout)
            yout[(((size_t)n * TSTEPS + t) * HC + hc) * HW + px] = hv;
    }
}

// ---------------- PDL launch wrapper ----------------
static void launch_conv_pdl(
    dim3 grid,
    const float* inA, int cinA, size_t inAStride,
    const float* inB, int cinB,
    const uint32_t* wt, const float* bias,
    const float* pre, size_t preStride,
    int HC, float* out, size_t outStride,
    const float* Wp, float* hout, float* c, float* yout, int t)
{
    cudaLaunchConfig_t cfg = {};
    cfg.gridDim = grid;
    cfg.blockDim = dim3(128, 1, 1);
    cfg.dynamicSmemBytes = 0;
    cfg.stream = 0;
    cudaLaunchAttribute attrs[1];
    attrs[0].id = cudaLaunchAttributeProgrammaticStreamSerialization;
    attrs[0].val.programmaticStreamSerializationAllowed = 1;
    cfg.attrs = attrs;
    cfg.numAttrs = 1;
    cudaLaunchKernelEx(&cfg, conv3x3_cell,
                       inA, cinA, inAStride, inB, cinB, wt, bias, pre, preStride,
                       HC, out, outStride, Wp, hout, c, yout, t);
}

// ---------------- host launch (R5 sequential structure + PDL) ----------------
extern "C" void kernel_launch(void* const* d_in, const int* in_sizes, int n_in,
                              void* d_out, int out_size)
{
    const float* x   = (const float*)d_in[0];
    const float* Wx0 = (const float*)d_in[1];
    const float* bx0 = (const float*)d_in[2];
    const float* Wh0 = (const float*)d_in[3];
    const float* Wp0 = (const float*)d_in[4];
    const float* Wx1 = (const float*)d_in[5];
    const float* bx1 = (const float*)d_in[6];
    const float* Wh1 = (const float*)d_in[7];
    const float* Wp1 = (const float*)d_in[8];
    const float* Wx2 = (const float*)d_in[9];
    const float* bx2 = (const float*)d_in[10];
    const float* Wh2 = (const float*)d_in[11];
    const float* Wp2 = (const float*)d_in[12];
    float* y = (float*)d_out;

    float *gx0, *state;
    uint32_t* wt;
    cudaGetSymbolAddress((void**)&gx0,   g_gx0);
    cudaGetSymbolAddress((void**)&state, g_state);
    cudaGetSymbolAddress((void**)&wt,    g_wt);

    float* h0buf[2] = { state + OFF_H0A, state + OFF_H0B };
    float* h1buf[2] = { state + OFF_H1A, state + OFF_H1B };
    float* h2buf[2] = { state + OFF_H2A, state + OFF_H2B };
    float* c0 = state + OFF_C0;
    float* c1 = state + OFF_C1;
    float* c2 = state + OFF_C2;

    init_zero_kernel<<<(NSTATE + 255) / 256, 256>>>(state, NSTATE);
    prep_all<<<(PREP_TOTAL + 255) / 256, 256>>>(Wx0, Wh0, Wx1, Wh1, Wx2, Wh2, wt);

    // batched gx0 = conv(x, Wx0) + bx0 over all B*T frames (plain path)
    launch_conv_pdl(dim3(BATCH * TSTEPS, HC0 / 8, 7),
        x, CIN0, (size_t)CIN0 * HW, nullptr, 0, wt + WOFF_GX0, bx0, nullptr, 0,
        HC0, gx0, (size_t)4 * HC0 * HW, nullptr, nullptr, nullptr, nullptr, 0);

    const size_t gx0FrameStride = (size_t)4 * HC0 * HW;
    const size_t gx0BatchStride = (size_t)TSTEPS * 4 * HC0 * HW;

    for (int t = 0; t < TSTEPS; ++t) {
        const int rb = t & 1;
        const int wb = rb ^ 1;
        float* h0r = h0buf[rb]; float* h0w = h0buf[wb];
        float* h1r = h1buf[rb]; float* h1w = h1buf[wb];
        float* h2r = h2buf[rb]; float* h2w = h2buf[wb];

        // layer 0: gates = gx0[b,t] + conv(h0_old, Wh0); fused LSTM
        launch_conv_pdl(dim3(BATCH, HC0 / 8, 7),
            h0r, HC0, (size_t)HC0 * HW, nullptr, 0, wt + WOFF_L0, nullptr,
            gx0 + (size_t)t * gx0FrameStride, gx0BatchStride,
            HC0, nullptr, 0, Wp0, h0w, c0, nullptr, t);

        // layer 1: gates = conv(h0_new, Wx1) + conv(h1_old, Wh1) + bx1
        launch_conv_pdl(dim3(BATCH, HC1 / 8, 7),
            h0w, HC0, (size_t)HC0 * HW, h1r, HC1, wt + WOFF_L1, bx1, nullptr, 0,
            HC1, nullptr, 0, Wp1, h1w, c1, nullptr, t);

        // layer 2: gates = conv(h1_new, Wx2) + conv(h2_old, Wh2) + bx2; emits y
        launch_conv_pdl(dim3(BATCH, HC2 / 8, 7),
            h1w, HC1, (size_t)HC1 * HW, h2r, HC2, wt + WOFF_L2, bx2, nullptr, 0,
            HC2, nullptr, 0, Wp2, h2w, c2, y, t);
    }
}

// round 17
// speedup vs baseline: 1.3171x; 1.3171x over previous
#include <cuda_runtime.h>
#include <cuda_bf16.h>
#include <math.h>
#include <stdint.h>

// ---------------- problem constants ----------------
#define BATCH 8
#define TSTEPS 16
#define CIN0 192
#define HC0 64
#define HC1 32
#define HC2 64
#define IMG_H 28
#define IMG_W 28
#define HW 784

// ---------------- device scratch (no allocs allowed) ----------------
__device__ float g_gx0[(size_t)BATCH * TSTEPS * 4 * HC0 * HW];

#define SZ0 (BATCH * HC0 * HW)
#define SZ1 (BATCH * HC1 * HW)
#define SZ2 (BATCH * HC2 * HW)
#define OFF_H0A 0
#define OFF_H0B (OFF_H0A + SZ0)
#define OFF_C0  (OFF_H0B + SZ0)
#define OFF_H1A (OFF_C0  + SZ0)
#define OFF_H1B (OFF_H1A + SZ1)
#define OFF_C1  (OFF_H1B + SZ1)
#define OFF_H2A (OFF_C1  + SZ1)
#define OFF_H2B (OFF_H2A + SZ2)
#define OFF_C2  (OFF_H2B + SZ2)
#define NSTATE  (OFF_C2  + SZ2)
__device__ float g_state[NSTATE];

// R5-layout weights (L0/L1/L2): [y][chunk8][tap][m(32)][ci(8)], oc=(m>>3)*HC+y*8+(m&7)
// M64-layout weights (gx0):     [y][chunk8][tap][m(64)][ci(8)], oc=(m>>4)*HC+y*16+(m&15)
#define WPC   2304
#define WPC64 4608
#define WOFF_GX64 0
#define WSZ_GX64 (4 * 24 * WPC64)       // y=4, chunks=24
#define WOFF_L0 (WOFF_GX64 + WSZ_GX64)
#define WSZ_L0  (8 * 8 * WPC)
#define WOFF_L1 (WOFF_L0 + WSZ_L0)
#define WSZ_L1  (4 * 12 * WPC)
#define WOFF_L2 (WOFF_L1 + WSZ_L1)
#define WSZ_L2  (8 * 12 * WPC)
#define WTOTAL  (WOFF_L2 + WSZ_L2)
__device__ uint32_t g_wt[WTOTAL];

__global__ void init_zero_kernel(float* p, int n) {
    int i = blockIdx.x * blockDim.x + threadIdx.x;
    if (i < n) p[i] = 0.f;
}

// ---------------- tf32 / cp.async helpers ----------------
__device__ __forceinline__ uint32_t f2tf32(float f) {
    uint32_t u;
    asm("cvt.rna.tf32.f32 %0, %1;" : "=r"(u) : "f"(f));
    return u;
}

__device__ __forceinline__ void cp_async16(uint32_t saddr, const void* gaddr) {
    asm volatile("cp.async.cg.shared.global [%0], [%1], 16;" :: "r"(saddr), "l"(gaddr));
}
#define CP_ASYNC_COMMIT() asm volatile("cp.async.commit_group;" ::: "memory")
#define CP_ASYNC_WAIT0()  asm volatile("cp.async.wait_group 0;" ::: "memory")

__device__ __forceinline__ void mma_tf32(float c[4],
                                         uint32_t a0, uint32_t a1, uint32_t a2, uint32_t a3,
                                         uint32_t b0, uint32_t b1) {
    asm volatile(
        "mma.sync.aligned.m16n8k8.row.col.f32.tf32.tf32.f32 "
        "{%0,%1,%2,%3}, {%4,%5,%6,%7}, {%8,%9}, {%0,%1,%2,%3};"
        : "+f"(c[0]), "+f"(c[1]), "+f"(c[2]), "+f"(c[3])
        : "r"(a0), "r"(a1), "r"(a2), "r"(a3), "r"(b0), "r"(b1));
}

__device__ __forceinline__ float sigmoidf_(float x) {
    return 1.0f / (1.0f + __expf(-x));
}

// ---------------- fused weight prep: both layouts, ONE launch ---------------
__device__ __forceinline__ void prep_one_r5(
    const float* __restrict__ WA, int cinA,
    const float* __restrict__ WB, int cinB,
    int HC, int chunks, uint32_t* __restrict__ dst, int idx)
{
    int ci  = idx & 7;
    int m   = (idx >> 3) & 31;
    int tap = (idx >> 8) % 9;
    int chy = idx / WPC;
    int ch  = chy % chunks;
    int y   = chy / chunks;
    int oc  = (m >> 3) * HC + y * 8 + (m & 7);
    int cg  = ch * 8 + ci;
    float w;
    if (cg < cinA) w = WA[((size_t)oc * cinA + cg) * 9 + tap];
    else           w = WB[((size_t)oc * cinB + (cg - cinA)) * 9 + tap];
    dst[idx] = f2tf32(w);
}

__device__ __forceinline__ void prep_one_m64(
    const float* __restrict__ WA, int cinA,
    int HC, int chunks, uint32_t* __restrict__ dst, int idx)
{
    int ci  = idx & 7;
    int m   = (idx >> 3) & 63;
    int tap = (idx >> 9) % 9;
    int chy = idx / WPC64;
    int ch  = chy % chunks;
    int y   = chy / chunks;
    int oc  = (m >> 4) * HC + y * 16 + (m & 15);
    int cg  = ch * 8 + ci;
    float w = WA[((size_t)oc * cinA + cg) * 9 + tap];
    dst[idx] = f2tf32(w);
}

__global__ void prep_all(
    const float* __restrict__ Wx0, const float* __restrict__ Wh0,
    const float* __restrict__ Wx1, const float* __restrict__ Wh1,
    const float* __restrict__ Wx2, const float* __restrict__ Wh2,
    uint32_t* __restrict__ wt)
{
    int i = blockIdx.x * blockDim.x + threadIdx.x;
    if (i < WSZ_GX64) { prep_one_m64(Wx0, CIN0, HC0, 24, wt + WOFF_GX64, i); return; }
    i -= WSZ_GX64;
    if (i < WSZ_L0)  { prep_one_r5(Wh0, HC0,  nullptr, 0, HC0,  8, wt + WOFF_L0, i); return; }
    i -= WSZ_L0;
    if (i < WSZ_L1)  { prep_one_r5(Wx1, HC0,  Wh1, HC1, HC1, 12, wt + WOFF_L1, i); return; }
    i -= WSZ_L1;
    if (i < WSZ_L2)  { prep_one_r5(Wx2, HC1,  Wh2, HC2, HC2, 12, wt + WOFF_L2, i); }
}
#define PREP_TOTAL WTOTAL

// ================= ENGINE 1: R5 conv (recurrent layers, verbatim) ===========
#define SIN_STR 200

struct SmemU {
    union {
        struct {
            uint32_t in[2][8 * SIN_STR];
            uint32_t w[2][WPC];
        } mm;
        float gates[4 * 8 * 112];
    };
};

__global__ void __launch_bounds__(128, 4) conv3x3_cell(
    const float* __restrict__ inA, int cinA, size_t inAStride,
    const float* __restrict__ inB, int cinB,
    const uint32_t* __restrict__ wt,
    const float* __restrict__ bias,
    const float* __restrict__ pre, size_t preStride,
    int HC,
    float* __restrict__ out, size_t outStride,   // plain path (hout == nullptr)
    const float* __restrict__ Wp,
    float* __restrict__ hout, float* __restrict__ c,
    float* __restrict__ yout, int t)
{
    __shared__ SmemU sm;

    const int n       = blockIdx.x;
    const int yb      = blockIdx.y;
    const int hcb     = yb * 8;
    const int rowbase = blockIdx.z * 4;

    const int tid    = threadIdx.x;
    const int lane   = tid & 31;
    const int wid    = tid >> 5;
    const int warp_m = wid & 1;
    const int warp_n = wid >> 1;
    const int g      = lane >> 2;
    const int ctg    = lane & 3;

    const int chunks = (cinA + cinB) >> 3;

    int off[7];
#pragma unroll
    for (int s = 0; s < 7; ++s) {
        int nl = warp_n * 56 + s * 8 + g;
        int r = nl / 28;
        off[s] = r * 30 + (nl - r * 28);
    }

    float acc[7][4];
#pragma unroll
    for (int s = 0; s < 7; ++s)
#pragma unroll
        for (int j = 0; j < 4; ++j) acc[s][j] = 0.f;

    float rin[12];
    uint4 rw4[5];

    auto load_chunk = [&](int ch) {
        const int cstart = ch * 8;
        const float* src = (cstart < cinA)
            ? inA + (size_t)n * inAStride + (size_t)cstart * HW
            : inB + ((size_t)n * cinB + (cstart - cinA)) * HW;
#pragma unroll
        for (int k = 0; k < 12; ++k) {
            int idx = tid + k * 128;
            float v = 0.f;
            if (idx < 1440) {
                int ci  = idx / 180;
                int rem = idx - ci * 180;
                int pr  = rem / 30;
                int gr  = rowbase + pr - 1;
                int gc  = (rem - pr * 30) - 1;
                if (gr >= 0 && gr < IMG_H && gc >= 0 && gc < IMG_W)
                    v = src[(size_t)ci * HW + gr * IMG_W + gc];
            }
            rin[k] = v;
        }
        const uint4* wsrc = (const uint4*)(wt + ((size_t)yb * chunks + ch) * WPC);
#pragma unroll
        for (int k = 0; k < 5; ++k) {
            int i4 = tid + k * 128;
            if (i4 < 576) rw4[k] = wsrc[i4];
        }
    };

    load_chunk(0);

    for (int ch = 0; ch < chunks; ++ch) {
        const int st = ch & 1;
#pragma unroll
        for (int k = 0; k < 12; ++k) {
            int idx = tid + k * 128;
            if (idx < 1440) {
                int ci  = idx / 180;
                int rem = idx - ci * 180;
                sm.mm.in[st][ci * SIN_STR + rem] = f2tf32(rin[k]);
            }
        }
#pragma unroll
        for (int k = 0; k < 5; ++k) {
            int i4 = tid + k * 128;
            if (i4 < 576) ((uint4*)sm.mm.w[st])[i4] = rw4[k];
        }
        __syncthreads();

        if (ch + 1 < chunks) load_chunk(ch + 1);

        const uint32_t* win = sm.mm.in[st];
        const uint32_t* ww  = sm.mm.w[st];
#pragma unroll
        for (int kr = 0; kr < 3; ++kr) {
#pragma unroll
            for (int kc = 0; kc < 3; ++kc) {
                const int tap = kr * 3 + kc;
                const uint32_t* wp = ww + tap * 256 + (warp_m * 16 + g) * 8 + ctg;
                uint32_t a0 = wp[0];
                uint32_t a1 = wp[64];
                uint32_t a2 = wp[4];
                uint32_t a3 = wp[68];
                const int bbase = ctg * SIN_STR + kr * 30 + kc;
#pragma unroll
                for (int s = 0; s < 7; ++s) {
                    uint32_t b0 = win[bbase + off[s]];
                    uint32_t b1 = win[bbase + off[s] + 4 * SIN_STR];
                    mma_tf32(acc[s], a0, a1, a2, a3, b0, b1);
                }
            }
        }
    }

    const int m0  = warp_m * 16 + g;
    const int oc0 = (m0 >> 3) * HC + hcb + (m0 & 7);
    const int m1  = m0 + 8;
    const int oc1 = (m1 >> 3) * HC + hcb + (m1 & 7);
    float bv0 = 0.f, bv1 = 0.f;
    if (bias) { bv0 = bias[oc0]; bv1 = bias[oc1]; }

    if (hout == nullptr) {
#pragma unroll
        for (int s = 0; s < 7; ++s) {
#pragma unroll
            for (int j = 0; j < 2; ++j) {
                int nl = warp_n * 56 + s * 8 + 2 * ctg + j;
                int r = nl / 28;
                int px = (rowbase + r) * IMG_W + (nl - r * 28);
                float v0 = acc[s][j]     + bv0;
                float v1 = acc[s][2 + j] + bv1;
                if (pre) {
                    v0 += pre[(size_t)n * preStride + (size_t)oc0 * HW + px];
                    v1 += pre[(size_t)n * preStride + (size_t)oc1 * HW + px];
                }
                out[(size_t)n * outStride + (size_t)oc0 * HW + px] = v0;
                out[(size_t)n * outStride + (size_t)oc1 * HW + px] = v1;
            }
        }
        return;
    }

    __syncthreads();
#pragma unroll
    for (int s = 0; s < 7; ++s) {
#pragma unroll
        for (int j = 0; j < 2; ++j) {
            int nl = warp_n * 56 + s * 8 + 2 * ctg + j;
            float v0 = acc[s][j]     + bv0;
            float v1 = acc[s][2 + j] + bv1;
            if (pre) {
                int r = nl / 28;
                int px = (rowbase + r) * IMG_W + (nl - r * 28);
                v0 += pre[(size_t)n * preStride + (size_t)oc0 * HW + px];
                v1 += pre[(size_t)n * preStride + (size_t)oc1 * HW + px];
            }
            sm.gates[((m0 >> 3) * 8 + (m0 & 7)) * 112 + nl] = v0;
            sm.gates[((m1 >> 3) * 8 + (m1 & 7)) * 112 + nl] = v1;
        }
    }
    __syncthreads();

#pragma unroll
    for (int k = 0; k < 7; ++k) {
        int e   = tid + k * 128;
        int hcl = e / 112;
        int nl  = e - hcl * 112;
        int r   = nl / 28;
        int px  = (rowbase + r) * IMG_W + (nl - r * 28);
        int hc  = hcb + hcl;

        float g0 = sm.gates[(0 * 8 + hcl) * 112 + nl];
        float g1 = sm.gates[(1 * 8 + hcl) * 112 + nl];
        float g2 = sm.gates[(2 * 8 + hcl) * 112 + nl];
        float g3 = sm.gates[(3 * 8 + hcl) * 112 + nl];

        size_t sidx = ((size_t)n * HC + hc) * HW + px;
        float cv = c[sidx];
        float pi = Wp[(size_t)(0 * HC + hc) * HW + px];
        float pf = Wp[(size_t)(1 * HC + hc) * HW + px];
        float po = Wp[(size_t)(2 * HC + hc) * HW + px];

        float gi = sigmoidf_(g0 + cv * pi);
        float gf = sigmoidf_(g1 + cv * pf);
        float cc = gf * cv + gi * tanhf(g2);
        float go = sigmoidf_(g3 + cc * po);
        float hv = go * tanhf(cc);

        c[sidx] = cc;
        hout[sidx] = hv;
        if (yout)
            yout[(((size_t)n * TSTEPS + t) * HC + hc) * HW + px] = hv;
    }
}

// ================= ENGINE 2: M=64/block conv (gx0 only, R11 verbatim) =======
#define SIN_STR64 184   // (184 mod 32)==24 -> conflict-free B LDS

struct SmemU64 {
    struct {
        uint32_t in[2][8 * SIN_STR64];
        uint32_t w[2][WPC64];
    } mm;
};

__global__ void __launch_bounds__(128, 4) conv3x3_m64(
    const float* __restrict__ inA, int cinA, size_t inAStride,
    const uint32_t* __restrict__ wt,
    const float* __restrict__ bias,
    int HC,
    float* __restrict__ out, size_t outStride)
{
    __shared__ SmemU64 sm;

    const int n       = blockIdx.x;
    const int yb      = blockIdx.y;
    const int hcb     = yb * 16;
    const int rowbase = blockIdx.z * 4;

    const int tid    = threadIdx.x;
    const int lane   = tid & 31;
    const int wid    = tid >> 5;
    const int warp_m = wid & 1;
    const int warp_n = wid >> 1;
    const int g      = lane >> 2;
    const int ctg    = lane & 3;

    const int chunks = cinA >> 3;

    uint32_t wsm[2];
    wsm[0] = (uint32_t)__cvta_generic_to_shared(sm.mm.w[0]);
    wsm[1] = (uint32_t)__cvta_generic_to_shared(sm.mm.w[1]);

    int off[7];
#pragma unroll
    for (int s = 0; s < 7; ++s) {
        int nl = warp_n * 56 + s * 8 + g;
        int r = nl / 28;
        off[s] = r * 30 + (nl - r * 28);
    }

    float acc[7][8];
#pragma unroll
    for (int s = 0; s < 7; ++s)
#pragma unroll
        for (int j = 0; j < 8; ++j) acc[s][j] = 0.f;

    float rin[12];

    auto load_chunk = [&](int ch) {
        const int st = ch & 1;
        const int cstart = ch * 8;
        const float* src = inA + (size_t)n * inAStride + (size_t)cstart * HW;
#pragma unroll
        for (int k = 0; k < 12; ++k) {
            int idx = tid + k * 128;
            float v = 0.f;
            if (idx < 1440) {
                int ci  = idx / 180;
                int rem = idx - ci * 180;
                int pr  = rem / 30;
                int gr  = rowbase + pr - 1;
                int gc  = (rem - pr * 30) - 1;
                if (gr >= 0 && gr < IMG_H && gc >= 0 && gc < IMG_W)
                    v = src[(size_t)ci * HW + gr * IMG_W + gc];
            }
            rin[k] = v;
        }
        const char* wsrc = (const char*)(wt + ((size_t)yb * chunks + ch) * WPC64);
#pragma unroll
        for (int k = 0; k < 9; ++k) {          // 1152 uint4 = 9 * 128
            int i4 = tid + k * 128;
            cp_async16(wsm[st] + i4 * 16, wsrc + (size_t)i4 * 16);
        }
        CP_ASYNC_COMMIT();
    };

    load_chunk(0);

    for (int ch = 0; ch < chunks; ++ch) {
        const int st = ch & 1;
#pragma unroll
        for (int k = 0; k < 12; ++k) {
            int idx = tid + k * 128;
            if (idx < 1440) {
                int ci  = idx / 180;
                int rem = idx - ci * 180;
                sm.mm.in[st][ci * SIN_STR64 + rem] = f2tf32(rin[k]);
            }
        }
        CP_ASYNC_WAIT0();
        __syncthreads();

        if (ch + 1 < chunks) load_chunk(ch + 1);

        const uint32_t* win = sm.mm.in[st];
        const uint32_t* ww  = sm.mm.w[st];
#pragma unroll
        for (int kr = 0; kr < 3; ++kr) {
#pragma unroll
            for (int kc = 0; kc < 3; ++kc) {
                const int tap = kr * 3 + kc;
                const uint32_t* wp = ww + tap * 512 + (warp_m * 32 + g) * 8 + ctg;
                uint32_t a00 = wp[0],   a01 = wp[64],  a02 = wp[4],   a03 = wp[68];
                uint32_t a10 = wp[128], a11 = wp[192], a12 = wp[132], a13 = wp[196];
                const int bbase = ctg * SIN_STR64 + kr * 30 + kc;
#pragma unroll
                for (int s = 0; s < 7; ++s) {
                    uint32_t b0 = win[bbase + off[s]];
                    uint32_t b1 = win[bbase + off[s] + 4 * SIN_STR64];
                    mma_tf32(acc[s],     a00, a01, a02, a03, b0, b1);
                    mma_tf32(acc[s] + 4, a10, a11, a12, a13, b0, b1);
                }
            }
        }
    }

    // epilogue (plain only): rows per thread:
    //  acc[s][0..1]: gate=2wm,   hcl=g ; acc[s][2..3]: gate=2wm,   hcl=g+8
    //  acc[s][4..5]: gate=2wm+1, hcl=g ; acc[s][6..7]: gate=2wm+1, hcl=g+8
    const int gate0 = 2 * warp_m;
    int ocr[4];
    ocr[0] = gate0 * HC + hcb + g;
    ocr[1] = gate0 * HC + hcb + g + 8;
    ocr[2] = (gate0 + 1) * HC + hcb + g;
    ocr[3] = (gate0 + 1) * HC + hcb + g + 8;
    float bv[4];
#pragma unroll
    for (int f = 0; f < 4; ++f) bv[f] = bias ? bias[ocr[f]] : 0.f;
    const int accidx[4] = {0, 2, 4, 6};

#pragma unroll
    for (int s = 0; s < 7; ++s) {
#pragma unroll
        for (int j = 0; j < 2; ++j) {
            int nl = warp_n * 56 + s * 8 + 2 * ctg + j;
            int r = nl / 28;
            int px = (rowbase + r) * IMG_W + (nl - r * 28);
#pragma unroll
            for (int f = 0; f < 4; ++f) {
                float v = acc[s][accidx[f] + j] + bv[f];
                out[(size_t)n * outStride + (size_t)ocr[f] * HW + px] = v;
            }
        }
    }
}

// ---------------- host launch ----------------
extern "C" void kernel_launch(void* const* d_in, const int* in_sizes, int n_in,
                              void* d_out, int out_size)
{
    const float* x   = (const float*)d_in[0];
    const float* Wx0 = (const float*)d_in[1];
    const float* bx0 = (const float*)d_in[2];
    const float* Wh0 = (const float*)d_in[3];
    const float* Wp0 = (const float*)d_in[4];
    const float* Wx1 = (const float*)d_in[5];
    const float* bx1 = (const float*)d_in[6];
    const float* Wh1 = (const float*)d_in[7];
    const float* Wp1 = (const float*)d_in[8];
    const float* Wx2 = (const float*)d_in[9];
    const float* bx2 = (const float*)d_in[10];
    const float* Wh2 = (const float*)d_in[11];
    const float* Wp2 = (const float*)d_in[12];
    float* y = (float*)d_out;

    float *gx0, *state;
    uint32_t* wt;
    cudaGetSymbolAddress((void**)&gx0,   g_gx0);
    cudaGetSymbolAddress((void**)&state, g_state);
    cudaGetSymbolAddress((void**)&wt,    g_wt);

    float* h0buf[2] = { state + OFF_H0A, state + OFF_H0B };
    float* h1buf[2] = { state + OFF_H1A, state + OFF_H1B };
    float* h2buf[2] = { state + OFF_H2A, state + OFF_H2B };
    float* c0 = state + OFF_C0;
    float* c1 = state + OFF_C1;
    float* c2 = state + OFF_C2;

    init_zero_kernel<<<(NSTATE + 255) / 256, 256>>>(state, NSTATE);
    prep_all<<<(PREP_TOTAL + 255) / 256, 256>>>(Wx0, Wh0, Wx1, Wh1, Wx2, Wh2, wt);

    // batched gx0 via M=64 engine (throughput-bound segment)
    conv3x3_m64<<<dim3(BATCH * TSTEPS, HC0 / 16, 7), 128>>>(
        x, CIN0, (size_t)CIN0 * HW, wt + WOFF_GX64, bx0,
        HC0, gx0, (size_t)4 * HC0 * HW);

    const size_t gx0FrameStride = (size_t)4 * HC0 * HW;
    const size_t gx0BatchStride = (size_t)TSTEPS * 4 * HC0 * HW;

    for (int t = 0; t < TSTEPS; ++t) {
        const int rb = t & 1;
        const int wb = rb ^ 1;
        float* h0r = h0buf[rb]; float* h0w = h0buf[wb];
        float* h1r = h1buf[rb]; float* h1w = h1buf[wb];
        float* h2r = h2buf[rb]; float* h2w = h2buf[wb];

        // layer 0: gates = gx0[b,t] + conv(h0_old, Wh0); fused LSTM
        conv3x3_cell<<<dim3(BATCH, HC0 / 8, 7), 128>>>(
            h0r, HC0, (size_t)HC0 * HW, nullptr, 0, wt + WOFF_L0, nullptr,
            gx0 + (size_t)t * gx0FrameStride, gx0BatchStride,
            HC0, nullptr, 0, Wp0, h0w, c0, nullptr, t);

        // layer 1: gates = conv(h0_new, Wx1) + conv(h1_old, Wh1) + bx1
        conv3x3_cell<<<dim3(BATCH, HC1 / 8, 7), 128>>>(
            h0w, HC0, (size_t)HC0 * HW, h1r, HC1, wt + WOFF_L1, bx1, nullptr, 0,
            HC1, nullptr, 0, Wp1, h1w, c1, nullptr, t);

        // layer 2: gates = conv(h1_new, Wx2) + conv(h2_old, Wh2) + bx2; emits y
        conv3x3_cell<<<dim3(BATCH, HC2 / 8, 7), 128>>>(
            h1w, HC1, (size_t)HC1 * HW, h2r, HC2, wt + WOFF_L2, bx2, nullptr, 0,
            HC2, nullptr, 0, Wp2, h2w, c2, y, t);
    }
}